// round 13
// baseline (speedup 1.0000x reference)
#include <cuda_runtime.h>
#include <math.h>

// Problem constants
#define S_LEN 4096
#define BATCH 8
#define EDIM 1024
#define NH 16
#define HD 64          // head_dim D
#define KP 64          // proj dim K
#define TWOK 128
#define MROWS (S_LEN * BATCH)   // 32768

// Output layout: s [B,H,2K,D] (1048576), z [B,H,2K] (16384), rm [H,K,D] (65536)
#define OUT_S_ELEMS (BATCH * NH * TWOK * HD)   // 1048576
#define OUT_Z_ELEMS (BATCH * NH * TWOK)        // 16384
#define OUT_RM_ELEMS (NH * KP * HD)            // 65536

// Scratch (device globals — no allocation allowed)
__device__ float g_C[EDIM * EDIM];                     // combined proj weights [1024,1024]
__device__ float g_cbias[EDIM];                        // combined proj bias
__device__ float g_phi[(size_t)MROWS * (NH * TWOK)];   // [M, 2048]  (256 MiB)
__device__ float g_v[(size_t)MROWS * EDIM];            // [M, 1024]  (128 MiB)

// ---------------------------------------------------------------------------
// Prep: C[j,e] = 0.125 * sum_d rm[h,kk,d] * Wk[h*64+d, e],  j = h*64+kk
//       cbias[j] = 0.125 * sum_d rm[h,kk,d] * bk[h*64+d]
// ---------------------------------------------------------------------------
__global__ __launch_bounds__(256) void prep_C_kernel(
    const float* __restrict__ Wk, const float* __restrict__ bk,
    const float* __restrict__ rm)
{
    int j = blockIdx.x;          // 0..1023
    int h = j >> 6;
    __shared__ float rrow[64];
    int tid = threadIdx.x;
    if (tid < 64) rrow[tid] = rm[j * 64 + tid];
    __syncthreads();

    int e0 = tid * 4;
    float a0 = 0.f, a1 = 0.f, a2 = 0.f, a3 = 0.f;
    #pragma unroll 8
    for (int d = 0; d < 64; ++d) {
        float r = rrow[d];
        const float4 w = *(const float4*)(Wk + (size_t)(h * 64 + d) * EDIM + e0);
        a0 += r * w.x; a1 += r * w.y; a2 += r * w.z; a3 += r * w.w;
    }
    float4 out = make_float4(0.125f * a0, 0.125f * a1, 0.125f * a2, 0.125f * a3);
    *(float4*)(g_C + (size_t)j * EDIM + e0) = out;

    if (tid == 0) {
        float cb = 0.f;
        for (int d = 0; d < 64; ++d) cb += rrow[d] * bk[h * 64 + d];
        g_cbias[j] = 0.125f * cb;
    }
}

// Copy rm / TAU (TAU = 1) to output tail
__global__ void copy_rm_kernel(const float* __restrict__ rm, float* __restrict__ out)
{
    int i = blockIdx.x * 256 + threadIdx.x;
    if (i < OUT_RM_ELEMS) out[i] = rm[i];
}

// ---------------------------------------------------------------------------
// Fused GEMM: columns [0,1024) -> proj (via g_C) -> phi = sin/cos epilogue
//             columns [1024,2048) -> v (via Wv) + bv
// 128x128x16 tiling, 256 threads, 8x8 per thread, fp32.
// ---------------------------------------------------------------------------
#define BM 128
#define BN 128
#define BK 16

__global__ __launch_bounds__(256) void fused_gemm_kernel(
    const float* __restrict__ A,     // enc [M, 1024]
    const float* __restrict__ Wv,    // [1024, 1024]
    const float* __restrict__ bv,
    const unsigned char* __restrict__ mask)  // [S,B] bytes (bool)
{
    __shared__ float As[BK][BM];
    __shared__ float Bs[BK][BN];

    int tid = threadIdx.x;
    int row0 = blockIdx.x * BM;
    int col0 = blockIdx.y * BN;          // 0..2047
    bool isProj = (col0 < EDIM);
    const float* Bmat = isProj ? g_C : Wv;
    int bcol0 = isProj ? col0 : (col0 - EDIM);

    float acc[8][8];
    #pragma unroll
    for (int i = 0; i < 8; ++i)
        #pragma unroll
        for (int j = 0; j < 8; ++j) acc[i][j] = 0.f;

    int tx = tid & 15, ty = tid >> 4;

    for (int k0 = 0; k0 < EDIM; k0 += BK) {
        #pragma unroll
        for (int l = 0; l < 2; ++l) {
            int slot = tid + l * 256;
            int m = slot >> 2;
            int kq = (slot & 3) * 4;
            float4 a = *(const float4*)(A + (size_t)(row0 + m) * EDIM + k0 + kq);
            As[kq + 0][m] = a.x; As[kq + 1][m] = a.y;
            As[kq + 2][m] = a.z; As[kq + 3][m] = a.w;
        }
        #pragma unroll
        for (int l = 0; l < 2; ++l) {
            int slot = tid + l * 256;
            int n = slot >> 2;
            int kq = (slot & 3) * 4;
            float4 b = *(const float4*)(Bmat + (size_t)(bcol0 + n) * EDIM + k0 + kq);
            Bs[kq + 0][n] = b.x; Bs[kq + 1][n] = b.y;
            Bs[kq + 2][n] = b.z; Bs[kq + 3][n] = b.w;
        }
        __syncthreads();

        #pragma unroll
        for (int k = 0; k < BK; ++k) {
            float ra[8], rb[8];
            #pragma unroll
            for (int i = 0; i < 8; ++i) ra[i] = As[k][ty * 8 + i];
            #pragma unroll
            for (int j = 0; j < 8; ++j) rb[j] = Bs[k][tx * 8 + j];
            #pragma unroll
            for (int i = 0; i < 8; ++i)
                #pragma unroll
                for (int j = 0; j < 8; ++j)
                    acc[i][j] += ra[i] * rb[j];
        }
        __syncthreads();
    }

    if (isProj) {
        #pragma unroll
        for (int i = 0; i < 8; ++i) {
            int r = row0 + ty * 8 + i;          // r = s*B + b
            float mz = mask[r] ? 0.f : 1.f;
            #pragma unroll
            for (int j = 0; j < 8; ++j) {
                int n = col0 + tx * 8 + j;      // 0..1023 = h*64 + kk
                float p = acc[i][j] + g_cbias[n];
                float sn, cs;
                sincosf(p, &sn, &cs);
                int h = n >> 6, kk = n & 63;
                size_t base = (size_t)r * (NH * TWOK) + h * TWOK + kk;
                g_phi[base]      = sn * 0.125f * mz;
                g_phi[base + 64] = cs * 0.125f * mz;
            }
        }
    } else {
        #pragma unroll
        for (int i = 0; i < 8; ++i) {
            int r = row0 + ty * 8 + i;
            #pragma unroll
            for (int j = 0; j < 8; ++j) {
                int n = bcol0 + tx * 8 + j;
                g_v[(size_t)r * EDIM + n] = acc[i][j] + bv[n];
            }
        }
    }
}

// ---------------------------------------------------------------------------
// Reduction: for each (b,h): s[128,64] = phi_bh^T @ v_bh over S=4096 rows,
//            z[128] = column sums of phi_bh.
// One block per (b,h). 256 threads; each owns 8 kk x 4 d accumulators.
// ---------------------------------------------------------------------------
__global__ __launch_bounds__(256) void reduce_sz_kernel(
    float* __restrict__ out_s, float* __restrict__ out_z)
{
    int bh = blockIdx.x;       // 0..127
    int b = bh >> 4, h = bh & 15;
    int tid = threadIdx.x;
    int kk0 = (tid & 15) * 8;
    int d0  = (tid >> 4) * 4;

    __shared__ float sph[32][TWOK];  // 16 KB
    __shared__ float sv[32][HD];     // 8 KB

    float acc[8][4];
    #pragma unroll
    for (int i = 0; i < 8; ++i)
        #pragma unroll
        for (int j = 0; j < 4; ++j) acc[i][j] = 0.f;
    float zacc[8];
    #pragma unroll
    for (int i = 0; i < 8; ++i) zacc[i] = 0.f;

    for (int s0 = 0; s0 < S_LEN; s0 += 32) {
        // load phi tile: 32 rows x 128 floats = 1024 float4
        #pragma unroll
        for (int l = 0; l < 4; ++l) {
            int slot = tid + l * 256;
            int ss = slot >> 5;       // 32 float4 per row
            int c4 = slot & 31;
            const float4* src = (const float4*)(g_phi +
                ((size_t)(s0 + ss) * BATCH + b) * (NH * TWOK) + h * TWOK) + c4;
            ((float4*)&sph[ss][0])[c4] = *src;
        }
        // load v tile: 32 rows x 64 floats = 512 float4
        #pragma unroll
        for (int l = 0; l < 2; ++l) {
            int slot = tid + l * 256;
            int ss = slot >> 4;       // 16 float4 per row
            int c4 = slot & 15;
            const float4* src = (const float4*)(g_v +
                ((size_t)(s0 + ss) * BATCH + b) * EDIM + h * HD) + c4;
            ((float4*)&sv[ss][0])[c4] = *src;
        }
        __syncthreads();

        #pragma unroll 4
        for (int ss = 0; ss < 32; ++ss) {
            float pv[4];
            #pragma unroll
            for (int j = 0; j < 4; ++j) pv[j] = sv[ss][d0 + j];
            #pragma unroll
            for (int i = 0; i < 8; ++i) {
                float pk = sph[ss][kk0 + i];
                if (d0 == 0) zacc[i] += pk;
                #pragma unroll
                for (int j = 0; j < 4; ++j) acc[i][j] += pk * pv[j];
            }
        }
        __syncthreads();
    }

    size_t sbase = (size_t)bh * TWOK * HD;
    #pragma unroll
    for (int i = 0; i < 8; ++i)
        #pragma unroll
        for (int j = 0; j < 4; ++j)
            out_s[sbase + (size_t)(kk0 + i) * HD + d0 + j] = acc[i][j];

    if (d0 == 0) {
        #pragma unroll
        for (int i = 0; i < 8; ++i)
            out_z[bh * TWOK + kk0 + i] = zacc[i];
    }
}

// ---------------------------------------------------------------------------
extern "C" void kernel_launch(void* const* d_in, const int* in_sizes, int n_in,
                              void* d_out, int out_size)
{
    const float* enc = (const float*)d_in[0];
    const float* Wk  = (const float*)d_in[1];
    const float* bk  = (const float*)d_in[2];
    const float* Wv  = (const float*)d_in[3];
    const float* bv  = (const float*)d_in[4];
    const float* rm  = (const float*)d_in[5];
    const unsigned char* mask = (const unsigned char*)d_in[6];
    float* out = (float*)d_out;

    float* out_s  = out;
    float* out_z  = out + OUT_S_ELEMS;
    float* out_rm = out + OUT_S_ELEMS + OUT_Z_ELEMS;

    prep_C_kernel<<<EDIM, 256>>>(Wk, bk, rm);
    copy_rm_kernel<<<(OUT_RM_ELEMS + 255) / 256, 256>>>(rm, out_rm);

    dim3 grid(MROWS / BM, (2 * EDIM) / BN);   // 256 x 16
    fused_gemm_kernel<<<grid, 256>>>(enc, Wv, bv, mask);

    reduce_sz_kernel<<<BATCH * NH, 256>>>(out_s, out_z);
}